// round 6
// baseline (speedup 1.0000x reference)
#include <cuda_runtime.h>
#include <math.h>
#include <stdint.h>

#define B_    8
#define N_    1024
#define DIM_  768
#define H_    8
#define HD_   96
#define E_    24
#define NT    (B_*N_)      /* 8192 tokens */
#define NA    (NT*H_)      /* 65536 assignments */
#define SCALE_ 0.10206207261596575f  /* 96^-0.5 */

/* ------------------------- scratch (device globals) ------------------------- */
__device__ float g_gate[NA];
__device__ float g_me[E_];
__device__ float g_z;
__device__ int   g_ecount[E_];
__device__ int   g_elist[E_*NA];
__device__ float g_k[NT*HD_];
__device__ float g_v[NT*HD_];
__device__ float g_q[(size_t)NA*HD_];
__device__ float g_o[(size_t)NA*HD_];

__device__ __forceinline__ uint32_t f2tf32(float f) {
    uint32_t r;
    asm("cvt.rna.tf32.f32 %0, %1;" : "=r"(r) : "f"(f));
    return r;
}

__device__ __forceinline__ void mma_tf32(float* d, const uint32_t* a, const uint32_t* b) {
    asm("mma.sync.aligned.m16n8k8.row.col.f32.tf32.tf32.f32 "
        "{%0,%1,%2,%3}, {%4,%5,%6,%7}, {%8,%9}, {%0,%1,%2,%3};"
        : "+f"(d[0]), "+f"(d[1]), "+f"(d[2]), "+f"(d[3])
        : "r"(a[0]), "r"(a[1]), "r"(a[2]), "r"(a[3]), "r"(b[0]), "r"(b[1]));
}

/* ------------------------------- zero counters ------------------------------ */
__global__ void zero_kernel() {
    int i = threadIdx.x;
    if (i < E_) { g_me[i] = 0.f; g_ecount[i] = 0; }
    if (i == 0) g_z = 0.f;
}

__global__ void zero_out_kernel(float* __restrict__ out, int n) {
    int i = blockIdx.x * 256 + threadIdx.x;
    if (i < n) out[i] = 0.f;
}

/* --------------------- gating: logits, softmax, top-8, lists (fp32) --------- */
__global__ void gate_kernel(const float* __restrict__ x,
                            const float* __restrict__ Wg,
                            const int*   __restrict__ task_p) {
    __shared__ float sme[E_];
    __shared__ float sz;
    __shared__ int   scnt[E_];
    __shared__ int   sbase[E_];
    int tid  = threadIdx.x;
    int warp = tid >> 5;
    int lane = tid & 31;
    int t = blockIdx.x * 8 + warp;

    if (tid < E_) { sme[tid] = 0.f; scnt[tid] = 0; }
    if (tid == 0) sz = 0.f;
    __syncthreads();

    int task = *task_p;
    const float* wg = Wg + (size_t)task * DIM_ * E_;
    const float* xr = x + (size_t)t * DIM_;

    float acc = 0.f;
    if (lane < E_) {
        #pragma unroll 4
        for (int d = 0; d < DIM_; d++) acc += xr[d] * wg[d * E_ + lane];
    }
    float logit = (lane < E_) ? acc : -1e30f;

    float m = logit;
    #pragma unroll
    for (int o = 16; o >= 1; o >>= 1) m = fmaxf(m, __shfl_xor_sync(0xffffffffu, m, o));
    float p = (lane < E_) ? expf(logit - m) : 0.f;
    float s = p;
    #pragma unroll
    for (int o = 16; o >= 1; o >>= 1) s += __shfl_xor_sync(0xffffffffu, s, o);
    float prob = p / s;
    float lse = m + logf(s);
    if (lane == 0) atomicAdd(&sz, lse * lse);
    if (lane < E_) atomicAdd(&sme[lane], prob);

    float val = (lane < E_) ? prob : -1.f;
    float sel_g = 0.f; int sel_e = 0;
    #pragma unroll
    for (int it = 0; it < H_; it++) {
        float mm = val;
        #pragma unroll
        for (int o = 16; o >= 1; o >>= 1) mm = fmaxf(mm, __shfl_xor_sync(0xffffffffu, mm, o));
        unsigned msk = __ballot_sync(0xffffffffu, val == mm);
        int src = __ffs(msk) - 1;
        if (lane == src) val = -1.f;
        if (lane == it) { sel_e = src; sel_g = mm; }
    }
    float gv = (lane < H_) ? sel_g : 0.f;
    #pragma unroll
    for (int o = 16; o >= 1; o >>= 1) gv += __shfl_xor_sync(0xffffffffu, gv, o);
    float denom = gv + 1e-6f;

    int pos = 0;
    if (lane < H_) pos = atomicAdd(&scnt[sel_e], 1);
    __syncthreads();
    if (tid < E_) sbase[tid] = atomicAdd(&g_ecount[tid], scnt[tid]);
    __syncthreads();
    if (lane < H_) {
        int a = t * H_ + lane;
        g_gate[a] = sel_g / denom;
        g_elist[sel_e * NA + sbase[sel_e] + pos] = a;
    }
    if (tid < E_) atomicAdd(&g_me[tid], sme[tid]);
    if (tid == 0) atomicAdd(&g_z, sz);
}

/* ----------------- kv projection, tf32 mma: x @ Wkv + b --------------------- */
/* tile 64 rows x 96 cols, grid (128, 2); warps: 4 row-grp x 2 col-grp; K=64   */
__global__ void __launch_bounds__(256) kv_tc_kernel(const float* __restrict__ x,
                                                    const float* __restrict__ Wkv,
                                                    const float* __restrict__ bkv) {
    __shared__ uint32_t xs[64 * 68];
    __shared__ uint32_t wsT[96 * 68];
    int r0 = blockIdx.x * 64;
    int c0 = blockIdx.y * 96;
    int tid = threadIdx.x;
    int wid = tid >> 5, lane = tid & 31;
    int rg = wid & 3, cg = wid >> 2;
    int g = lane >> 2, tig = lane & 3;
    int row_a0 = rg * 16 + g, row_a1 = row_a0 + 8;

    float acc[6][4];
    #pragma unroll
    for (int nn = 0; nn < 6; nn++)
        #pragma unroll
        for (int r = 0; r < 4; r++) acc[nn][r] = 0.f;

    for (int k0 = 0; k0 < DIM_; k0 += 64) {
        __syncthreads();
        for (int i = tid; i < 64 * 64; i += 256) {
            int r = i >> 6, k = i & 63;
            xs[r * 68 + k] = f2tf32(x[(size_t)(r0 + r) * DIM_ + k0 + k]);
        }
        for (int i = tid; i < 96 * 64; i += 256) {
            int k = i / 96, c = i % 96;
            wsT[c * 68 + k] = f2tf32(Wkv[(size_t)(k0 + k) * (2 * HD_) + c0 + c]);
        }
        __syncthreads();
        #pragma unroll
        for (int kk = 0; kk < 8; kk++) {
            uint32_t a[4];
            a[0] = xs[row_a0 * 68 + kk * 8 + tig];
            a[1] = xs[row_a1 * 68 + kk * 8 + tig];
            a[2] = xs[row_a0 * 68 + kk * 8 + tig + 4];
            a[3] = xs[row_a1 * 68 + kk * 8 + tig + 4];
            #pragma unroll
            for (int nn = 0; nn < 6; nn++) {
                uint32_t bb[2];
                bb[0] = wsT[(cg * 48 + nn * 8 + g) * 68 + kk * 8 + tig];
                bb[1] = wsT[(cg * 48 + nn * 8 + g) * 68 + kk * 8 + tig + 4];
                mma_tf32(acc[nn], a, bb);
            }
        }
    }

    float* dst = (c0 == 0) ? g_k : g_v;
    int r_g0 = r0 + row_a0, r_g1 = r0 + row_a1;
    #pragma unroll
    for (int nn = 0; nn < 6; nn++) {
        int c = cg * 48 + nn * 8 + tig * 2;
        float b0 = bkv[c0 + c], b1 = bkv[c0 + c + 1];
        dst[(size_t)r_g0 * HD_ + c]     = acc[nn][0] + b0;
        dst[(size_t)r_g0 * HD_ + c + 1] = acc[nn][1] + b1;
        dst[(size_t)r_g1 * HD_ + c]     = acc[nn][2] + b0;
        dst[(size_t)r_g1 * HD_ + c + 1] = acc[nn][3] + b1;
    }
}

/* ---------- grouped q projection, tf32 mma: gathered x @ W1[e] -------------- */
/* tile 128 assignments x 96 cols, grid (512, 24); 8 warps x 16 rows; K=64     */
#define Q_SMEM_WORDS (128*68 + 96*68)
__global__ void __launch_bounds__(256) q_tc_kernel(const float* __restrict__ x,
                                                   const float* __restrict__ W1) {
    int e = blockIdx.y;
    int count = g_ecount[e];
    int base = blockIdx.x * 128;
    if (base >= count) return;

    extern __shared__ uint32_t qsm[];
    uint32_t* xs  = qsm;                 /* [128][68] */
    uint32_t* wsT = qsm + 128 * 68;      /* [96][68]  */
    __shared__ int s_a[128];
    int tid = threadIdx.x;
    if (tid < 128) {
        int idx = base + tid; if (idx >= count) idx = count - 1;
        s_a[tid] = g_elist[e * NA + idx];
    }
    int wid = tid >> 5, lane = tid & 31;
    int g = lane >> 2, tig = lane & 3;
    int row_a0 = wid * 16 + g, row_a1 = row_a0 + 8;
    const float* w1 = W1 + (size_t)e * DIM_ * HD_;

    float acc[12][4];
    #pragma unroll
    for (int nn = 0; nn < 12; nn++)
        #pragma unroll
        for (int r = 0; r < 4; r++) acc[nn][r] = 0.f;

    for (int k0 = 0; k0 < DIM_; k0 += 64) {
        __syncthreads();   /* also covers s_a visibility on first iter */
        for (int i = tid; i < 128 * 64; i += 256) {
            int r = i >> 6, k = i & 63;
            int tok = s_a[r] >> 3;
            xs[r * 68 + k] = f2tf32(x[(size_t)tok * DIM_ + k0 + k]);
        }
        for (int i = tid; i < 96 * 64; i += 256) {
            int k = i / 96, c = i % 96;
            wsT[c * 68 + k] = f2tf32(w1[(size_t)(k0 + k) * HD_ + c]);
        }
        __syncthreads();
        #pragma unroll
        for (int kk = 0; kk < 8; kk++) {
            uint32_t a[4];
            a[0] = xs[row_a0 * 68 + kk * 8 + tig];
            a[1] = xs[row_a1 * 68 + kk * 8 + tig];
            a[2] = xs[row_a0 * 68 + kk * 8 + tig + 4];
            a[3] = xs[row_a1 * 68 + kk * 8 + tig + 4];
            #pragma unroll
            for (int nn = 0; nn < 12; nn++) {
                uint32_t bb[2];
                bb[0] = wsT[(nn * 8 + g) * 68 + kk * 8 + tig];
                bb[1] = wsT[(nn * 8 + g) * 68 + kk * 8 + tig + 4];
                mma_tf32(acc[nn], a, bb);
            }
        }
    }

    bool ok0 = (base + row_a0 < count), ok1 = (base + row_a1 < count);
    int a0 = s_a[row_a0], a1 = s_a[row_a1];
    #pragma unroll
    for (int nn = 0; nn < 12; nn++) {
        int c = nn * 8 + tig * 2;
        if (ok0) {
            g_q[(size_t)a0 * HD_ + c]     = acc[nn][0];
            g_q[(size_t)a0 * HD_ + c + 1] = acc[nn][1];
        }
        if (ok1) {
            g_q[(size_t)a1 * HD_ + c]     = acc[nn][2];
            g_q[(size_t)a1 * HD_ + c + 1] = acc[nn][3];
        }
    }
}

/* ---------------- fused flash attention, tf32 mma.sync ---------------------- */
#define QS_STRIDE 100
#define KS_STRIDE 100
#define VS_STRIDE 104
#define PS_STRIDE 68
#define ATTN_SMEM_WORDS (128*QS_STRIDE + 64*KS_STRIDE + 64*VS_STRIDE + 8*16*PS_STRIDE)

__global__ void __launch_bounds__(256, 1) attn_tc_kernel() {
    extern __shared__ uint32_t smu[];
    uint32_t* qs = smu;
    uint32_t* ks = qs + 128 * QS_STRIDE;
    uint32_t* vs = ks + 64 * KS_STRIDE;
    uint32_t* ps = vs + 64 * VS_STRIDE;

    int it = blockIdx.x, bh = blockIdx.y;
    int b = bh >> 3, h = bh & 7;
    int i0 = it * 128;
    int tid  = threadIdx.x;
    int wid  = tid >> 5;
    int lane = tid & 31;
    int g    = lane >> 2;
    int tig  = lane & 3;
    uint32_t* pw = ps + wid * 16 * PS_STRIDE;

    for (int idx = tid; idx < 128 * 96; idx += 256) {
        int i = idx / 96, d = idx % 96;
        qs[i * QS_STRIDE + d] =
            f2tf32(g_q[((size_t)(b * N_ + i0 + i) * H_ + h) * HD_ + d] * SCALE_);
    }

    float m0 = -1e30f, m1 = -1e30f, l0 = 0.f, l1 = 0.f;
    float o_acc[12][4];
    #pragma unroll
    for (int nn = 0; nn < 12; nn++)
        #pragma unroll
        for (int r = 0; r < 4; r++) o_acc[nn][r] = 0.f;

    int row_a0 = wid * 16 + g;
    int row_a1 = wid * 16 + g + 8;

    for (int jt = 0; jt < 16; jt++) {
        int j0 = jt * 64;
        __syncthreads();
        for (int idx = tid; idx < 64 * 96; idx += 256) {
            int j = idx / 96, d = idx % 96;
            int r = b * N_ + j0 + j;
            ks[j * KS_STRIDE + d] = f2tf32(g_k[(size_t)r * HD_ + d]);
            vs[j * VS_STRIDE + d] = f2tf32(g_v[(size_t)r * HD_ + d]);
        }
        __syncthreads();

        float sv[8][4];
        #pragma unroll
        for (int nn = 0; nn < 8; nn++)
            #pragma unroll
            for (int r = 0; r < 4; r++) sv[nn][r] = 0.f;

        #pragma unroll
        for (int kk = 0; kk < 12; kk++) {
            uint32_t a[4];
            a[0] = qs[row_a0 * QS_STRIDE + kk * 8 + tig];
            a[1] = qs[row_a1 * QS_STRIDE + kk * 8 + tig];
            a[2] = qs[row_a0 * QS_STRIDE + kk * 8 + tig + 4];
            a[3] = qs[row_a1 * QS_STRIDE + kk * 8 + tig + 4];
            #pragma unroll
            for (int nn = 0; nn < 8; nn++) {
                uint32_t bb[2];
                bb[0] = ks[(nn * 8 + g) * KS_STRIDE + kk * 8 + tig];
                bb[1] = ks[(nn * 8 + g) * KS_STRIDE + kk * 8 + tig + 4];
                mma_tf32(sv[nn], a, bb);
            }
        }

        float rmax0 = -1e30f, rmax1 = -1e30f;
        #pragma unroll
        for (int nn = 0; nn < 8; nn++) {
            rmax0 = fmaxf(rmax0, fmaxf(sv[nn][0], sv[nn][1]));
            rmax1 = fmaxf(rmax1, fmaxf(sv[nn][2], sv[nn][3]));
        }
        #pragma unroll
        for (int o = 1; o <= 2; o <<= 1) {
            rmax0 = fmaxf(rmax0, __shfl_xor_sync(0xffffffffu, rmax0, o));
            rmax1 = fmaxf(rmax1, __shfl_xor_sync(0xffffffffu, rmax1, o));
        }
        float nm0 = fmaxf(m0, rmax0), nm1 = fmaxf(m1, rmax1);
        float corr0 = __expf(m0 - nm0), corr1 = __expf(m1 - nm1);
        float rs0 = 0.f, rs1 = 0.f;
        #pragma unroll
        for (int nn = 0; nn < 8; nn++) {
            float p00 = __expf(sv[nn][0] - nm0);
            float p01 = __expf(sv[nn][1] - nm0);
            float p10 = __expf(sv[nn][2] - nm1);
            float p11 = __expf(sv[nn][3] - nm1);
            rs0 += p00 + p01; rs1 += p10 + p11;
            int c = nn * 8 + tig * 2;
            pw[g * PS_STRIDE + c]           = f2tf32(p00);
            pw[g * PS_STRIDE + c + 1]       = f2tf32(p01);
            pw[(g + 8) * PS_STRIDE + c]     = f2tf32(p10);
            pw[(g + 8) * PS_STRIDE + c + 1] = f2tf32(p11);
        }
        #pragma unroll
        for (int o = 1; o <= 2; o <<= 1) {
            rs0 += __shfl_xor_sync(0xffffffffu, rs0, o);
            rs1 += __shfl_xor_sync(0xffffffffu, rs1, o);
        }
        l0 = l0 * corr0 + rs0;  m0 = nm0;
        l1 = l1 * corr1 + rs1;  m1 = nm1;
        #pragma unroll
        for (int nn = 0; nn < 12; nn++) {
            o_acc[nn][0] *= corr0; o_acc[nn][1] *= corr0;
            o_acc[nn][2] *= corr1; o_acc[nn][3] *= corr1;
        }
        __syncwarp();

        #pragma unroll
        for (int kk = 0; kk < 8; kk++) {
            uint32_t a[4];
            a[0] = pw[g * PS_STRIDE + kk * 8 + tig];
            a[1] = pw[(g + 8) * PS_STRIDE + kk * 8 + tig];
            a[2] = pw[g * PS_STRIDE + kk * 8 + tig + 4];
            a[3] = pw[(g + 8) * PS_STRIDE + kk * 8 + tig + 4];
            #pragma unroll
            for (int nn = 0; nn < 12; nn++) {
                uint32_t bb[2];
                bb[0] = vs[(kk * 8 + tig) * VS_STRIDE + nn * 8 + g];
                bb[1] = vs[(kk * 8 + tig + 4) * VS_STRIDE + nn * 8 + g];
                mma_tf32(o_acc[nn], a, bb);
            }
        }
        __syncwarp();
    }

    float inv0 = 1.f / l0, inv1 = 1.f / l1;
    int tok0 = b * N_ + i0 + row_a0;
    int tok1 = b * N_ + i0 + row_a1;
    #pragma unroll
    for (int nn = 0; nn < 12; nn++) {
        int c = nn * 8 + tig * 2;
        size_t o0 = ((size_t)tok0 * H_ + h) * HD_ + c;
        size_t o1 = ((size_t)tok1 * H_ + h) * HD_ + c;
        g_o[o0]     = o_acc[nn][0] * inv0;
        g_o[o0 + 1] = o_acc[nn][1] * inv0;
        g_o[o1]     = o_acc[nn][2] * inv1;
        g_o[o1 + 1] = o_acc[nn][3] * inv1;
    }
}

/* ------ grouped reduce, tf32 mma: out[t] += gate[a]*o[a] @ W2[e] ------------ */
#define RED_SMEM_WORDS (64*100 + 128*100)
__global__ void __launch_bounds__(256) red_tc_kernel(const float* __restrict__ W2,
                                                     float* __restrict__ out) {
    int e = blockIdx.y;
    int count = g_ecount[e];
    int base = blockIdx.x * 64;
    if (base >= count) return;

    extern __shared__ uint32_t rsm[];
    uint32_t* osT = rsm;
    uint32_t* w2T = rsm + 64 * 100;
    __shared__ int s_a[64];

    int tid = threadIdx.x;
    if (tid < 64) {
        int idx = base + tid; if (idx >= count) idx = count - 1;
        s_a[tid] = g_elist[e * NA + idx];
    }
    __syncthreads();

    for (int idx = tid; idx < 64 * 96; idx += 256) {
        int r = idx / 96, d = idx % 96;
        int a = s_a[r];
        osT[r * 100 + d] = f2tf32(g_gate[a] * g_o[(size_t)a * HD_ + d]);
    }

    int wid = tid >> 5, lane = tid & 31;
    int mg = wid & 3, ch = wid >> 2;
    int g = lane >> 2, tig = lane & 3;
    int row_a0 = mg * 16 + g, row_a1 = row_a0 + 8;
    const float* w2 = W2 + (size_t)e * HD_ * DIM_;

    bool ok0 = (base + row_a0 < count), ok1 = (base + row_a1 < count);
    int t0 = s_a[row_a0] >> 3, t1 = s_a[row_a1] >> 3;

    for (int ct = 0; ct < 6; ct++) {
        __syncthreads();
        for (int idx = tid; idx < 128 * 96; idx += 256) {
            int k = idx >> 7, c = idx & 127;
            w2T[c * 100 + k] = f2tf32(w2[(size_t)k * DIM_ + ct * 128 + c]);
        }
        __syncthreads();

        float acc[8][4];
        #pragma unroll
        for (int nn = 0; nn < 8; nn++)
            #pragma unroll
            for (int r = 0; r < 4; r++) acc[nn][r] = 0.f;

        #pragma unroll
        for (int kk = 0; kk < 12; kk++) {
            uint32_t a[4];
            a[0] = osT[row_a0 * 100 + kk * 8 + tig];
            a[1] = osT[row_a1 * 100 + kk * 8 + tig];
            a[2] = osT[row_a0 * 100 + kk * 8 + tig + 4];
            a[3] = osT[row_a1 * 100 + kk * 8 + tig + 4];
            #pragma unroll
            for (int nn = 0; nn < 8; nn++) {
                uint32_t bb[2];
                bb[0] = w2T[(ch * 64 + nn * 8 + g) * 100 + kk * 8 + tig];
                bb[1] = w2T[(ch * 64 + nn * 8 + g) * 100 + kk * 8 + tig + 4];
                mma_tf32(acc[nn], a, bb);
            }
        }

        #pragma unroll
        for (int nn = 0; nn < 8; nn++) {
            int c = ct * 128 + ch * 64 + nn * 8 + tig * 2;
            if (ok0) {
                atomicAdd(&out[(size_t)t0 * DIM_ + c],     acc[nn][0]);
                atomicAdd(&out[(size_t)t0 * DIM_ + c + 1], acc[nn][1]);
            }
            if (ok1) {
                atomicAdd(&out[(size_t)t1 * DIM_ + c],     acc[nn][2]);
                atomicAdd(&out[(size_t)t1 * DIM_ + c + 1], acc[nn][3]);
            }
        }
    }
}

/* ------------------------------- aux loss ----------------------------------- */
__global__ void aux_kernel(float* __restrict__ out, int out_size) {
    if (threadIdx.x == 0) {
        float mesum = 0.f;
        for (int e = 0; e < E_; e++) mesum += g_me[e];
        float sw = 0.f;
        for (int e = 0; e < E_; e++)
            sw += (g_me[e] / mesum) * ((float)g_ecount[e] / (float)NA);
        sw *= (float)E_;
        float z = g_z / (float)NT;
        float aux = 0.1f * sw + 0.001f * z;
        if (out_size > NT * DIM_) out[out_size - 1] = aux;
    }
}

/* -------------------------------- launch ------------------------------------ */
extern "C" void kernel_launch(void* const* d_in, const int* in_sizes, int n_in,
                              void* d_out, int out_size) {
    const float* x    = (const float*)d_in[0];
    const float* Wg   = (const float*)d_in[1];
    const float* W1   = (const float*)d_in[2];
    const float* W2   = (const float*)d_in[3];
    const float* Wkv  = (const float*)d_in[4];
    const float* bkv  = (const float*)d_in[5];
    const int*   task = (const int*)d_in[6];
    float* out = (float*)d_out;

    cudaFuncSetAttribute(attn_tc_kernel,
                         cudaFuncAttributeMaxDynamicSharedMemorySize,
                         ATTN_SMEM_WORDS * (int)sizeof(uint32_t));
    cudaFuncSetAttribute(red_tc_kernel,
                         cudaFuncAttributeMaxDynamicSharedMemorySize,
                         RED_SMEM_WORDS * (int)sizeof(uint32_t));
    cudaFuncSetAttribute(q_tc_kernel,
                         cudaFuncAttributeMaxDynamicSharedMemorySize,
                         Q_SMEM_WORDS * (int)sizeof(uint32_t));

    zero_kernel<<<1, 32>>>();
    zero_out_kernel<<<(out_size + 255) / 256, 256>>>(out, out_size);
    gate_kernel<<<NT / 8, 256>>>(x, Wg, task);
    kv_tc_kernel<<<dim3(NT / 64, 2), 256>>>(x, Wkv, bkv);
    q_tc_kernel<<<dim3(512, E_), 256, Q_SMEM_WORDS * sizeof(uint32_t)>>>(x, W1);
    attn_tc_kernel<<<dim3(8, B_ * H_), 256, ATTN_SMEM_WORDS * sizeof(uint32_t)>>>();
    red_tc_kernel<<<dim3(1024, E_), 256, RED_SMEM_WORDS * sizeof(uint32_t)>>>(W2, out);
    aux_kernel<<<1, 32>>>(out, out_size);
}

// round 7
// speedup vs baseline: 1.0522x; 1.0522x over previous
#include <cuda_runtime.h>
#include <math.h>
#include <stdint.h>

#define B_    8
#define N_    1024
#define DIM_  768
#define H_    8
#define HD_   96
#define E_    24
#define NT    (B_*N_)      /* 8192 tokens */
#define NA    (NT*H_)      /* 65536 assignments */
#define SCALE_ 0.10206207261596575f  /* 96^-0.5 */

/* ------------------------- scratch (device globals) ------------------------- */
__device__ float g_gate[NA];
__device__ float g_me[E_];
__device__ float g_z;
__device__ int   g_ecount[E_];
__device__ int   g_elist[E_*NA];
__device__ float g_k[NT*HD_];
__device__ float g_v[NT*HD_];
__device__ float g_q[(size_t)NA*HD_];
__device__ float g_o[(size_t)NA*HD_];

__device__ __forceinline__ uint32_t f2tf32(float f) {
    uint32_t r;
    asm("cvt.rna.tf32.f32 %0, %1;" : "=r"(r) : "f"(f));
    return r;
}

__device__ __forceinline__ void mma_tf32(float* d, const uint32_t* a, const uint32_t* b) {
    asm("mma.sync.aligned.m16n8k8.row.col.f32.tf32.tf32.f32 "
        "{%0,%1,%2,%3}, {%4,%5,%6,%7}, {%8,%9}, {%0,%1,%2,%3};"
        : "+f"(d[0]), "+f"(d[1]), "+f"(d[2]), "+f"(d[3])
        : "r"(a[0]), "r"(a[1]), "r"(a[2]), "r"(a[3]), "r"(b[0]), "r"(b[1]));
}

/* vector fp32 reduction to global (sm_90+): one LSU op for two adds */
__device__ __forceinline__ void red_add_v2(float* addr, float a, float b) {
    asm volatile("red.global.add.v2.f32 [%0], {%1, %2};"
                 :: "l"(addr), "f"(a), "f"(b) : "memory");
}

/* ------------------------------- zero counters ------------------------------ */
__global__ void zero_kernel() {
    int i = threadIdx.x;
    if (i < E_) { g_me[i] = 0.f; g_ecount[i] = 0; }
    if (i == 0) g_z = 0.f;
}

__global__ void zero_out_kernel(float* __restrict__ out, int n) {
    int i = blockIdx.x * 256 + threadIdx.x;
    if (i < n) out[i] = 0.f;
}

/* --------------------- gating: logits, softmax, top-8, lists (fp32) --------- */
__global__ void gate_kernel(const float* __restrict__ x,
                            const float* __restrict__ Wg,
                            const int*   __restrict__ task_p) {
    __shared__ float sme[E_];
    __shared__ float sz;
    __shared__ int   scnt[E_];
    __shared__ int   sbase[E_];
    int tid  = threadIdx.x;
    int warp = tid >> 5;
    int lane = tid & 31;
    int t = blockIdx.x * 8 + warp;

    if (tid < E_) { sme[tid] = 0.f; scnt[tid] = 0; }
    if (tid == 0) sz = 0.f;
    __syncthreads();

    int task = *task_p;
    const float* wg = Wg + (size_t)task * DIM_ * E_;
    const float* xr = x + (size_t)t * DIM_;

    float acc = 0.f;
    if (lane < E_) {
        #pragma unroll 4
        for (int d = 0; d < DIM_; d++) acc += xr[d] * wg[d * E_ + lane];
    }
    float logit = (lane < E_) ? acc : -1e30f;

    float m = logit;
    #pragma unroll
    for (int o = 16; o >= 1; o >>= 1) m = fmaxf(m, __shfl_xor_sync(0xffffffffu, m, o));
    float p = (lane < E_) ? expf(logit - m) : 0.f;
    float s = p;
    #pragma unroll
    for (int o = 16; o >= 1; o >>= 1) s += __shfl_xor_sync(0xffffffffu, s, o);
    float prob = p / s;
    float lse = m + logf(s);
    if (lane == 0) atomicAdd(&sz, lse * lse);
    if (lane < E_) atomicAdd(&sme[lane], prob);

    float val = (lane < E_) ? prob : -1.f;
    float sel_g = 0.f; int sel_e = 0;
    #pragma unroll
    for (int it = 0; it < H_; it++) {
        float mm = val;
        #pragma unroll
        for (int o = 16; o >= 1; o >>= 1) mm = fmaxf(mm, __shfl_xor_sync(0xffffffffu, mm, o));
        unsigned msk = __ballot_sync(0xffffffffu, val == mm);
        int src = __ffs(msk) - 1;
        if (lane == src) val = -1.f;
        if (lane == it) { sel_e = src; sel_g = mm; }
    }
    float gv = (lane < H_) ? sel_g : 0.f;
    #pragma unroll
    for (int o = 16; o >= 1; o >>= 1) gv += __shfl_xor_sync(0xffffffffu, gv, o);
    float denom = gv + 1e-6f;

    int pos = 0;
    if (lane < H_) pos = atomicAdd(&scnt[sel_e], 1);
    __syncthreads();
    if (tid < E_) sbase[tid] = atomicAdd(&g_ecount[tid], scnt[tid]);
    __syncthreads();
    if (lane < H_) {
        int a = t * H_ + lane;
        g_gate[a] = sel_g / denom;
        g_elist[sel_e * NA + sbase[sel_e] + pos] = a;
    }
    if (tid < E_) atomicAdd(&g_me[tid], sme[tid]);
    if (tid == 0) atomicAdd(&g_z, sz);
}

/* ----------------- kv projection (R2 SIMT, measured 100.8us) ---------------- */
/* tile 64x64, grid (128, 3), 256 threads, 4x4 per-thread */
__global__ void kv_kernel(const float* __restrict__ x,
                          const float* __restrict__ Wkv,
                          const float* __restrict__ bkv) {
    __shared__ float xsT[32][68];
    __shared__ float ws[32][68];
    int r0 = blockIdx.x * 64;
    int c0 = blockIdx.y * 64;
    int tid = threadIdx.x;
    int ty = tid >> 4, tx = tid & 15;
    float acc[4][4] = {};

    for (int k0 = 0; k0 < DIM_; k0 += 32) {
        for (int i = tid; i < 64 * 32; i += 256) {
            int r = i >> 5, k = i & 31;
            xsT[k][r] = x[(size_t)(r0 + r) * DIM_ + k0 + k];
        }
        for (int i = tid; i < 32 * 64; i += 256) {
            int k = i >> 6, c = i & 63;
            ws[k][c] = Wkv[(size_t)(k0 + k) * (2 * HD_) + c0 + c];
        }
        __syncthreads();
        #pragma unroll
        for (int k = 0; k < 32; k++) {
            float4 a4 = *(const float4*)&xsT[k][ty * 4];
            float4 b4 = *(const float4*)&ws[k][tx * 4];
            float av[4] = {a4.x, a4.y, a4.z, a4.w};
            float bv[4] = {b4.x, b4.y, b4.z, b4.w};
            #pragma unroll
            for (int i = 0; i < 4; i++)
                #pragma unroll
                for (int j = 0; j < 4; j++) acc[i][j] += av[i] * bv[j];
        }
        __syncthreads();
    }
    #pragma unroll
    for (int i = 0; i < 4; i++) {
        int r = r0 + ty * 4 + i;
        #pragma unroll
        for (int j = 0; j < 4; j++) {
            int c = c0 + tx * 4 + j;
            float v = acc[i][j] + bkv[c];
            if (c < HD_) g_k[(size_t)r * HD_ + c]          = v;
            else         g_v[(size_t)r * HD_ + (c - HD_)]  = v;
        }
    }
}

/* ---------- grouped q projection, tf32 mma: gathered x @ W1[e] -------------- */
/* tile 128 assignments x 96 cols, grid (512, 24); 8 warps x 16 rows; K=64     */
#define Q_SMEM_WORDS (128*68 + 96*68)
__global__ void __launch_bounds__(256) q_tc_kernel(const float* __restrict__ x,
                                                   const float* __restrict__ W1) {
    int e = blockIdx.y;
    int count = g_ecount[e];
    int base = blockIdx.x * 128;
    if (base >= count) return;

    extern __shared__ uint32_t qsm[];
    uint32_t* xs  = qsm;                 /* [128][68] */
    uint32_t* wsT = qsm + 128 * 68;      /* [96][68]  */
    __shared__ int s_a[128];
    int tid = threadIdx.x;
    if (tid < 128) {
        int idx = base + tid; if (idx >= count) idx = count - 1;
        s_a[tid] = g_elist[e * NA + idx];
    }
    int wid = tid >> 5, lane = tid & 31;
    int g = lane >> 2, tig = lane & 3;
    int row_a0 = wid * 16 + g, row_a1 = row_a0 + 8;
    const float* w1 = W1 + (size_t)e * DIM_ * HD_;

    float acc[12][4];
    #pragma unroll
    for (int nn = 0; nn < 12; nn++)
        #pragma unroll
        for (int r = 0; r < 4; r++) acc[nn][r] = 0.f;

    for (int k0 = 0; k0 < DIM_; k0 += 64) {
        __syncthreads();   /* also covers s_a visibility on first iter */
        for (int i = tid; i < 128 * 64; i += 256) {
            int r = i >> 6, k = i & 63;
            int tok = s_a[r] >> 3;
            xs[r * 68 + k] = f2tf32(x[(size_t)tok * DIM_ + k0 + k]);
        }
        for (int i = tid; i < 96 * 64; i += 256) {
            int k = i / 96, c = i % 96;
            wsT[c * 68 + k] = f2tf32(w1[(size_t)(k0 + k) * HD_ + c]);
        }
        __syncthreads();
        #pragma unroll
        for (int kk = 0; kk < 8; kk++) {
            uint32_t a[4];
            a[0] = xs[row_a0 * 68 + kk * 8 + tig];
            a[1] = xs[row_a1 * 68 + kk * 8 + tig];
            a[2] = xs[row_a0 * 68 + kk * 8 + tig + 4];
            a[3] = xs[row_a1 * 68 + kk * 8 + tig + 4];
            #pragma unroll
            for (int nn = 0; nn < 12; nn++) {
                uint32_t bb[2];
                bb[0] = wsT[(nn * 8 + g) * 68 + kk * 8 + tig];
                bb[1] = wsT[(nn * 8 + g) * 68 + kk * 8 + tig + 4];
                mma_tf32(acc[nn], a, bb);
            }
        }
    }

    bool ok0 = (base + row_a0 < count), ok1 = (base + row_a1 < count);
    int a0 = s_a[row_a0], a1 = s_a[row_a1];
    #pragma unroll
    for (int nn = 0; nn < 12; nn++) {
        int c = nn * 8 + tig * 2;
        if (ok0) {
            g_q[(size_t)a0 * HD_ + c]     = acc[nn][0];
            g_q[(size_t)a0 * HD_ + c + 1] = acc[nn][1];
        }
        if (ok1) {
            g_q[(size_t)a1 * HD_ + c]     = acc[nn][2];
            g_q[(size_t)a1 * HD_ + c + 1] = acc[nn][3];
        }
    }
}

/* ---------------- fused flash attention, tf32 mma.sync ---------------------- */
#define QS_STRIDE 100
#define KS_STRIDE 100
#define VS_STRIDE 104
#define PS_STRIDE 68
#define ATTN_SMEM_WORDS (128*QS_STRIDE + 64*KS_STRIDE + 64*VS_STRIDE + 8*16*PS_STRIDE)

__global__ void __launch_bounds__(256, 1) attn_tc_kernel() {
    extern __shared__ uint32_t smu[];
    uint32_t* qs = smu;
    uint32_t* ks = qs + 128 * QS_STRIDE;
    uint32_t* vs = ks + 64 * KS_STRIDE;
    uint32_t* ps = vs + 64 * VS_STRIDE;

    int it = blockIdx.x, bh = blockIdx.y;
    int b = bh >> 3, h = bh & 7;
    int i0 = it * 128;
    int tid  = threadIdx.x;
    int wid  = tid >> 5;
    int lane = tid & 31;
    int g    = lane >> 2;
    int tig  = lane & 3;
    uint32_t* pw = ps + wid * 16 * PS_STRIDE;

    for (int idx = tid; idx < 128 * 96; idx += 256) {
        int i = idx / 96, d = idx % 96;
        qs[i * QS_STRIDE + d] =
            f2tf32(g_q[((size_t)(b * N_ + i0 + i) * H_ + h) * HD_ + d] * SCALE_);
    }

    float m0 = -1e30f, m1 = -1e30f, l0 = 0.f, l1 = 0.f;
    float o_acc[12][4];
    #pragma unroll
    for (int nn = 0; nn < 12; nn++)
        #pragma unroll
        for (int r = 0; r < 4; r++) o_acc[nn][r] = 0.f;

    int row_a0 = wid * 16 + g;
    int row_a1 = wid * 16 + g + 8;

    for (int jt = 0; jt < 16; jt++) {
        int j0 = jt * 64;
        __syncthreads();
        for (int idx = tid; idx < 64 * 96; idx += 256) {
            int j = idx / 96, d = idx % 96;
            int r = b * N_ + j0 + j;
            ks[j * KS_STRIDE + d] = f2tf32(g_k[(size_t)r * HD_ + d]);
            vs[j * VS_STRIDE + d] = f2tf32(g_v[(size_t)r * HD_ + d]);
        }
        __syncthreads();

        float sv[8][4];
        #pragma unroll
        for (int nn = 0; nn < 8; nn++)
            #pragma unroll
            for (int r = 0; r < 4; r++) sv[nn][r] = 0.f;

        #pragma unroll
        for (int kk = 0; kk < 12; kk++) {
            uint32_t a[4];
            a[0] = qs[row_a0 * QS_STRIDE + kk * 8 + tig];
            a[1] = qs[row_a1 * QS_STRIDE + kk * 8 + tig];
            a[2] = qs[row_a0 * QS_STRIDE + kk * 8 + tig + 4];
            a[3] = qs[row_a1 * QS_STRIDE + kk * 8 + tig + 4];
            #pragma unroll
            for (int nn = 0; nn < 8; nn++) {
                uint32_t bb[2];
                bb[0] = ks[(nn * 8 + g) * KS_STRIDE + kk * 8 + tig];
                bb[1] = ks[(nn * 8 + g) * KS_STRIDE + kk * 8 + tig + 4];
                mma_tf32(sv[nn], a, bb);
            }
        }

        float rmax0 = -1e30f, rmax1 = -1e30f;
        #pragma unroll
        for (int nn = 0; nn < 8; nn++) {
            rmax0 = fmaxf(rmax0, fmaxf(sv[nn][0], sv[nn][1]));
            rmax1 = fmaxf(rmax1, fmaxf(sv[nn][2], sv[nn][3]));
        }
        #pragma unroll
        for (int o = 1; o <= 2; o <<= 1) {
            rmax0 = fmaxf(rmax0, __shfl_xor_sync(0xffffffffu, rmax0, o));
            rmax1 = fmaxf(rmax1, __shfl_xor_sync(0xffffffffu, rmax1, o));
        }
        float nm0 = fmaxf(m0, rmax0), nm1 = fmaxf(m1, rmax1);
        float corr0 = __expf(m0 - nm0), corr1 = __expf(m1 - nm1);
        float rs0 = 0.f, rs1 = 0.f;
        #pragma unroll
        for (int nn = 0; nn < 8; nn++) {
            float p00 = __expf(sv[nn][0] - nm0);
            float p01 = __expf(sv[nn][1] - nm0);
            float p10 = __expf(sv[nn][2] - nm1);
            float p11 = __expf(sv[nn][3] - nm1);
            rs0 += p00 + p01; rs1 += p10 + p11;
            int c = nn * 8 + tig * 2;
            pw[g * PS_STRIDE + c]           = f2tf32(p00);
            pw[g * PS_STRIDE + c + 1]       = f2tf32(p01);
            pw[(g + 8) * PS_STRIDE + c]     = f2tf32(p10);
            pw[(g + 8) * PS_STRIDE + c + 1] = f2tf32(p11);
        }
        #pragma unroll
        for (int o = 1; o <= 2; o <<= 1) {
            rs0 += __shfl_xor_sync(0xffffffffu, rs0, o);
            rs1 += __shfl_xor_sync(0xffffffffu, rs1, o);
        }
        l0 = l0 * corr0 + rs0;  m0 = nm0;
        l1 = l1 * corr1 + rs1;  m1 = nm1;
        #pragma unroll
        for (int nn = 0; nn < 12; nn++) {
            o_acc[nn][0] *= corr0; o_acc[nn][1] *= corr0;
            o_acc[nn][2] *= corr1; o_acc[nn][3] *= corr1;
        }
        __syncwarp();

        #pragma unroll
        for (int kk = 0; kk < 8; kk++) {
            uint32_t a[4];
            a[0] = pw[g * PS_STRIDE + kk * 8 + tig];
            a[1] = pw[(g + 8) * PS_STRIDE + kk * 8 + tig];
            a[2] = pw[g * PS_STRIDE + kk * 8 + tig + 4];
            a[3] = pw[(g + 8) * PS_STRIDE + kk * 8 + tig + 4];
            #pragma unroll
            for (int nn = 0; nn < 12; nn++) {
                uint32_t bb[2];
                bb[0] = vs[(kk * 8 + tig) * VS_STRIDE + nn * 8 + g];
                bb[1] = vs[(kk * 8 + tig + 4) * VS_STRIDE + nn * 8 + g];
                mma_tf32(o_acc[nn], a, bb);
            }
        }
        __syncwarp();
    }

    float inv0 = 1.f / l0, inv1 = 1.f / l1;
    int tok0 = b * N_ + i0 + row_a0;
    int tok1 = b * N_ + i0 + row_a1;
    #pragma unroll
    for (int nn = 0; nn < 12; nn++) {
        int c = nn * 8 + tig * 2;
        size_t o0 = ((size_t)tok0 * H_ + h) * HD_ + c;
        size_t o1 = ((size_t)tok1 * H_ + h) * HD_ + c;
        g_o[o0]     = o_acc[nn][0] * inv0;
        g_o[o0 + 1] = o_acc[nn][1] * inv0;
        g_o[o1]     = o_acc[nn][2] * inv1;
        g_o[o1 + 1] = o_acc[nn][3] * inv1;
    }
}

/* ------ grouped reduce, tf32 mma: out[t] += gate[a]*o[a] @ W2[e] ------------ */
/* epilogue now uses red.global.add.v2.f32 — half the LSU atomic ops           */
#define RED_SMEM_WORDS (64*100 + 128*100)
__global__ void __launch_bounds__(256) red_tc_kernel(const float* __restrict__ W2,
                                                     float* __restrict__ out) {
    int e = blockIdx.y;
    int count = g_ecount[e];
    int base = blockIdx.x * 64;
    if (base >= count) return;

    extern __shared__ uint32_t rsm[];
    uint32_t* osT = rsm;
    uint32_t* w2T = rsm + 64 * 100;
    __shared__ int s_a[64];

    int tid = threadIdx.x;
    if (tid < 64) {
        int idx = base + tid; if (idx >= count) idx = count - 1;
        s_a[tid] = g_elist[e * NA + idx];
    }
    __syncthreads();

    for (int idx = tid; idx < 64 * 96; idx += 256) {
        int r = idx / 96, d = idx % 96;
        int a = s_a[r];
        osT[r * 100 + d] = f2tf32(g_gate[a] * g_o[(size_t)a * HD_ + d]);
    }

    int wid = tid >> 5, lane = tid & 31;
    int mg = wid & 3, ch = wid >> 2;
    int g = lane >> 2, tig = lane & 3;
    int row_a0 = mg * 16 + g, row_a1 = row_a0 + 8;
    const float* w2 = W2 + (size_t)e * HD_ * DIM_;

    bool ok0 = (base + row_a0 < count), ok1 = (base + row_a1 < count);
    int t0 = s_a[row_a0] >> 3, t1 = s_a[row_a1] >> 3;

    for (int ct = 0; ct < 6; ct++) {
        __syncthreads();
        for (int idx = tid; idx < 128 * 96; idx += 256) {
            int k = idx >> 7, c = idx & 127;
            w2T[c * 100 + k] = f2tf32(w2[(size_t)k * DIM_ + ct * 128 + c]);
        }
        __syncthreads();

        float acc[8][4];
        #pragma unroll
        for (int nn = 0; nn < 8; nn++)
            #pragma unroll
            for (int r = 0; r < 4; r++) acc[nn][r] = 0.f;

        #pragma unroll
        for (int kk = 0; kk < 12; kk++) {
            uint32_t a[4];
            a[0] = osT[row_a0 * 100 + kk * 8 + tig];
            a[1] = osT[row_a1 * 100 + kk * 8 + tig];
            a[2] = osT[row_a0 * 100 + kk * 8 + tig + 4];
            a[3] = osT[row_a1 * 100 + kk * 8 + tig + 4];
            #pragma unroll
            for (int nn = 0; nn < 8; nn++) {
                uint32_t bb[2];
                bb[0] = w2T[(ch * 64 + nn * 8 + g) * 100 + kk * 8 + tig];
                bb[1] = w2T[(ch * 64 + nn * 8 + g) * 100 + kk * 8 + tig + 4];
                mma_tf32(acc[nn], a, bb);
            }
        }

        #pragma unroll
        for (int nn = 0; nn < 8; nn++) {
            int c = ct * 128 + ch * 64 + nn * 8 + tig * 2;
            if (ok0) red_add_v2(&out[(size_t)t0 * DIM_ + c], acc[nn][0], acc[nn][1]);
            if (ok1) red_add_v2(&out[(size_t)t1 * DIM_ + c], acc[nn][2], acc[nn][3]);
        }
    }
}

/* ------------------------------- aux loss ----------------------------------- */
__global__ void aux_kernel(float* __restrict__ out, int out_size) {
    if (threadIdx.x == 0) {
        float mesum = 0.f;
        for (int e = 0; e < E_; e++) mesum += g_me[e];
        float sw = 0.f;
        for (int e = 0; e < E_; e++)
            sw += (g_me[e] / mesum) * ((float)g_ecount[e] / (float)NA);
        sw *= (float)E_;
        float z = g_z / (float)NT;
        float aux = 0.1f * sw + 0.001f * z;
        if (out_size > NT * DIM_) out[out_size - 1] = aux;
    }
}

/* -------------------------------- launch ------------------------------------ */
extern "C" void kernel_launch(void* const* d_in, const int* in_sizes, int n_in,
                              void* d_out, int out_size) {
    const float* x    = (const float*)d_in[0];
    const float* Wg   = (const float*)d_in[1];
    const float* W1   = (const float*)d_in[2];
    const float* W2   = (const float*)d_in[3];
    const float* Wkv  = (const float*)d_in[4];
    const float* bkv  = (const float*)d_in[5];
    const int*   task = (const int*)d_in[6];
    float* out = (float*)d_out;

    cudaFuncSetAttribute(attn_tc_kernel,
                         cudaFuncAttributeMaxDynamicSharedMemorySize,
                         ATTN_SMEM_WORDS * (int)sizeof(uint32_t));
    cudaFuncSetAttribute(red_tc_kernel,
                         cudaFuncAttributeMaxDynamicSharedMemorySize,
                         RED_SMEM_WORDS * (int)sizeof(uint32_t));
    cudaFuncSetAttribute(q_tc_kernel,
                         cudaFuncAttributeMaxDynamicSharedMemorySize,
                         Q_SMEM_WORDS * (int)sizeof(uint32_t));

    zero_kernel<<<1, 32>>>();
    zero_out_kernel<<<(out_size + 255) / 256, 256>>>(out, out_size);
    gate_kernel<<<NT / 8, 256>>>(x, Wg, task);
    kv_kernel<<<dim3(NT / 64, 3), 256>>>(x, Wkv, bkv);
    q_tc_kernel<<<dim3(512, E_), 256, Q_SMEM_WORDS * sizeof(uint32_t)>>>(x, W1);
    attn_tc_kernel<<<dim3(8, B_ * H_), 256, ATTN_SMEM_WORDS * sizeof(uint32_t)>>>();
    red_tc_kernel<<<dim3(1024, E_), 256, RED_SMEM_WORDS * sizeof(uint32_t)>>>(W2, out);
    aux_kernel<<<1, 32>>>(out, out_size);
}